// round 7
// baseline (speedup 1.0000x reference)
#include <cuda_runtime.h>
#include <math.h>
#include <stdint.h>

// ---------------------------------------------------------------------------
// Problem constants
// ---------------------------------------------------------------------------
#define N_ROWS 131072
#define D 64
#define K 512
#define TILE_M 128
#define NBLOCKS (N_ROWS / TILE_M)   // 1024
#define ST 144                      // row stride BYTES for A' / W' (128 data + 16 pad)

// Output layout: [xn | xn | proto | cvae | pdl]
#define XN2_OFF   ((long)N_ROWS * D)
#define PROTO_OFF (2L * N_ROWS * D)
#define CVAE_OFF  (PROTO_OFF + (long)N_ROWS * K)
#define PDL_OFF   (CVAE_OFF + 1)

// Shared memory layout (bytes)
#define OFF_A     0                  // int8 A' [128][ST]  rows = [xh(64B) | xl(64B)]
#define OFF_W     18432              // int8 W' [512][ST]  rows = [wl(64B) | wh(64B)]
#define OFF_B2    92160              // f32 [512]  exact ||w_j||^2
#define OFF_C1    94208              // f32 [512]  per-col dequant scale s_j/127
#define OFF_A2    96256              // f32 [128]
#define OFF_CMIN  96768              // u32 [512]
#define OFF_RMIN  98816              // u32 [128]
#define OFF_RED   99328              // f32 [128]
#define SMEM_TOTAL 99840

// Device scratch (no allocations allowed)
__device__ unsigned int g_colmin[K];
__device__ float        g_row_partial[NBLOCKS];
__device__ float        g_b2[K];
__device__ float        g_ws[K];               // s_j/127 = max|w|/(127*127)
__device__ uint4        g_W8[K * ST / 16];     // packed W' image, 73728 B

// ---------------------------------------------------------------------------
// Helpers (sm_80-level PTX only: ldmatrix + int8 mma.sync)
// ---------------------------------------------------------------------------
__device__ __forceinline__ uint32_t smem_u32(const void* p) {
    uint32_t a;
    asm("{ .reg .u64 t; cvta.to.shared.u64 t, %1; cvt.u32.u64 %0, t; }" : "=r"(a) : "l"(p));
    return a;
}
__device__ __forceinline__ void ldsm_x4(uint32_t* r, uint32_t addr) {
    asm volatile("ldmatrix.sync.aligned.m8n8.x4.shared.b16 {%0,%1,%2,%3}, [%4];"
                 : "=r"(r[0]), "=r"(r[1]), "=r"(r[2]), "=r"(r[3]) : "r"(addr));
}
__device__ __forceinline__ void mma_s8(int* d, const uint32_t* a, uint32_t b0, uint32_t b1) {
    asm volatile("mma.sync.aligned.m16n8k32.row.col.s32.s8.s8.s32 "
                 "{%0,%1,%2,%3}, {%4,%5,%6,%7}, {%8,%9}, {%0,%1,%2,%3};"
                 : "+r"(d[0]), "+r"(d[1]), "+r"(d[2]), "+r"(d[3])
                 : "r"(a[0]), "r"(a[1]), "r"(a[2]), "r"(a[3]), "r"(b0), "r"(b1));
}
__device__ __forceinline__ int pack4(int b0, int b1, int b2, int b3) {
    return (b0 & 0xFF) | ((b1 & 0xFF) << 8) | ((b2 & 0xFF) << 16) | ((b3 & 0xFF) << 24);
}

// ---------------------------------------------------------------------------
// Init: one warp per W row. Exact b2, dequant scale, int8 hi/lo quantization
// into the packed [wl|wh] image. 64 blocks x 256 threads.
// ---------------------------------------------------------------------------
__global__ void swav_init_kernel(const float* __restrict__ W) {
    int gt  = blockIdx.x * blockDim.x + threadIdx.x;
    int r   = gt >> 5;
    int lid = gt & 31;
    if (r >= K) return;

    float2 v = *(const float2*)&W[r * D + lid * 2];
    float s2 = fmaf(v.x, v.x, v.y * v.y);
    float mx = fmaxf(fabsf(v.x), fabsf(v.y));
    #pragma unroll
    for (int o = 16; o > 0; o >>= 1) {
        s2 += __shfl_xor_sync(0xffffffffu, s2, o);
        mx = fmaxf(mx, __shfl_xor_sync(0xffffffffu, mx, o));
    }
    mx = fmaxf(mx, 1e-30f);
    float invs = 127.0f / mx;

    int h0 = __float2int_rn(v.x * invs);
    int h1 = __float2int_rn(v.y * invs);
    int l0 = min(__float2int_rn(fmaf(v.x, invs, (float)(-h0)) * 256.0f), 127);
    int l1 = min(__float2int_rn(fmaf(v.y, invs, (float)(-h1)) * 256.0f), 127);

    unsigned short* img = (unsigned short*)g_W8;
    img[(r * ST + 2 * lid) >> 1]      = (unsigned short)((l0 & 0xFF) | ((l1 & 0xFF) << 8));
    img[(r * ST + 64 + 2 * lid) >> 1] = (unsigned short)((h0 & 0xFF) | ((h1 & 0xFF) << 8));

    if (lid == 0) {
        g_b2[r] = s2;
        // dot = (s_j / 127) * (i_hh + i_cross/256); s_j = mx/127
        g_ws[r] = mx / 16129.0f;      // mx / (127*127)
        g_colmin[r] = 0x7F800000u;
    }
}

// ---------------------------------------------------------------------------
// Main: per CTA 128 rows x all 512 prototypes.
// normalize (regs) -> xn x2 -> int8 hi/lo A' tile -> s8 MMA GEMM
// (hihi K=64 + concat-cross K=128 = 6 MMAs/frag) -> register epilogue.
// ---------------------------------------------------------------------------
__global__ __launch_bounds__(256, 1)
void swav_main_kernel(const float* __restrict__ x, float* __restrict__ out) {
    extern __shared__ __align__(16) char sm[];
    float*        b2s    = (float*)(sm + OFF_B2);
    float*        c1s    = (float*)(sm + OFF_C1);
    float*        a2s    = (float*)(sm + OFF_A2);
    unsigned int* cmin_s = (unsigned int*)(sm + OFF_CMIN);
    unsigned int* rmin_s = (unsigned int*)(sm + OFF_RMIN);
    float*        red    = (float*)(sm + OFF_RED);

    const uint32_t sb  = smem_u32(sm);
    const int t   = threadIdx.x;
    const int lid = t & 31;
    const int wid = t >> 5;
    const long row0 = (long)blockIdx.x * TILE_M;

    // ---- Phase 1: W' image -> smem (flat copy, identical stride); scalars ----
    {
        uint4* dst = (uint4*)(sm + OFF_W);
        #pragma unroll
        for (int i = 0; i < 18; ++i) dst[t + i * 256] = g_W8[t + i * 256];
    }
    for (int i = t; i < K; i += 256) {
        b2s[i] = g_b2[i];
        c1s[i] = g_ws[i];
        cmin_s[i] = 0x7F800000u;
    }
    if (t < TILE_M) rmin_s[t] = 0x7F800000u;

    // ---- Phase 2: load x, normalize in regs, write xn x2, quantize into A' ----
    {
        const float4* xg  = (const float4*)(x + row0 * D);
        float4* xn1 = (float4*)(out + row0 * D);
        float4* xn2 = (float4*)(out + XN2_OFF + row0 * D);
        float4 v[8]; float s[8];
        #pragma unroll
        for (int i = 0; i < 8; ++i) {
            int idx = t + i * 256;                    // [128 rows][16 float4]
            v[i] = xg[idx];
            s[i] = fmaf(v[i].x, v[i].x, fmaf(v[i].y, v[i].y,
                    fmaf(v[i].z, v[i].z, v[i].w * v[i].w)));
        }
        #pragma unroll
        for (int m = 1; m < 16; m <<= 1)
            #pragma unroll
            for (int i = 0; i < 8; ++i)
                s[i] += __shfl_xor_sync(0xffffffffu, s[i], m);
        #pragma unroll
        for (int i = 0; i < 8; ++i) {
            int idx = t + i * 256;
            int r = idx >> 4, c = idx & 15;
            float inv = 1.0f / fmaxf(sqrtf(s[i]), 1e-12f);
            float4 w4 = make_float4(v[i].x * inv, v[i].y * inv, v[i].z * inv, v[i].w * inv);
            xn1[idx] = w4;
            xn2[idx] = w4;
            if ((t & 15) == 0) a2s[r] = s[i] * inv * inv;

            int h0 = __float2int_rn(w4.x * 127.f), h1 = __float2int_rn(w4.y * 127.f);
            int h2 = __float2int_rn(w4.z * 127.f), h3 = __float2int_rn(w4.w * 127.f);
            int l0 = min(__float2int_rn(fmaf(w4.x, 127.f, (float)(-h0)) * 256.f), 127);
            int l1 = min(__float2int_rn(fmaf(w4.y, 127.f, (float)(-h1)) * 256.f), 127);
            int l2 = min(__float2int_rn(fmaf(w4.z, 127.f, (float)(-h2)) * 256.f), 127);
            int l3 = min(__float2int_rn(fmaf(w4.w, 127.f, (float)(-h3)) * 256.f), 127);
            *(int*)(sm + OFF_A + r * ST + 4 * c)      = pack4(h0, h1, h2, h3);
            *(int*)(sm + OFF_A + r * ST + 64 + 4 * c) = pack4(l0, l1, l2, l3);
        }
    }
    __syncthreads();

    // ---- Phase 3: int8 MMA GEMM + epilogue over 4 strips of 64 cols ----
    const int wy = wid & 3, wx = wid >> 2;
    const int m0 = wy * 32;

    const uint32_t a_base = sb + OFF_A + (uint32_t)(m0 + (lid & 15)) * ST + ((lid >> 4) * 16);
    const uint32_t b_rowi = ((lid >> 4) << 3) + (lid & 7);
    const uint32_t b_koff = ((lid >> 3) & 1) * 16;

    float a2r[2][2];
    #pragma unroll
    for (int mf = 0; mf < 2; ++mf) {
        a2r[mf][0] = a2s[m0 + mf * 16 + (lid >> 2)];
        a2r[mf][1] = a2s[m0 + mf * 16 + (lid >> 2) + 8];
    }
    float rowmin[4];
    #pragma unroll
    for (int j = 0; j < 4; ++j) rowmin[j] = 3.0e38f;

    #pragma unroll 1
    for (int strip = 0; strip < 4; ++strip) {
        const int nb = wx * 256 + strip * 64;
        int acc1[2][8][4], acc2[2][8][4];
        #pragma unroll
        for (int mf = 0; mf < 2; ++mf)
            #pragma unroll
            for (int p = 0; p < 8; ++p)
                #pragma unroll
                for (int q = 0; q < 4; ++q) { acc1[mf][p][q] = 0; acc2[mf][p][q] = 0; }

        // A fragments: [mf][kb], each ldsm.x4 = 16 rows x 32B
        uint32_t A[2][4][4];
        #pragma unroll
        for (int mf = 0; mf < 2; ++mf)
            #pragma unroll
            for (int kb = 0; kb < 4; ++kb)
                ldsm_x4(A[mf][kb], a_base + mf * 16 * ST + kb * 32);

        #pragma unroll
        for (int pg = 0; pg < 4; ++pg) {     // 16 cols per group
            const uint32_t wb = sb + OFF_W + (uint32_t)(nb + pg * 16 + b_rowi) * ST + b_koff;
            #pragma unroll
            for (int kb = 0; kb < 4; ++kb) {
                uint32_t Wf[4];
                ldsm_x4(Wf, wb + kb * 32);   // cols pg*16..+15, W' bytes kb*32..+31
                #pragma unroll
                for (int mf = 0; mf < 2; ++mf) {
                    // cross: A'(full K=128) x W'(full) = xh*wl + xl*wh
                    mma_s8(acc2[mf][2 * pg],     A[mf][kb], Wf[0], Wf[1]);
                    mma_s8(acc2[mf][2 * pg + 1], A[mf][kb], Wf[2], Wf[3]);
                    if (kb >= 2) {
                        // hi*hi: A bytes 0..63 (kb-2) x W bytes 64..127 (kb = wh)
                        mma_s8(acc1[mf][2 * pg],     A[mf][kb - 2], Wf[0], Wf[1]);
                        mma_s8(acc1[mf][2 * pg + 1], A[mf][kb - 2], Wf[2], Wf[3]);
                    }
                }
            }
        }

        // Epilogue: proto stores + z-mins from registers
        #pragma unroll
        for (int p = 0; p < 8; ++p) {
            const int c = nb + p * 8 + 2 * (lid & 3);
            const float c1a = c1s[c],     c2a = c1a * 0.00390625f;
            const float c1b = c1s[c + 1], c2b = c1b * 0.00390625f;
            const float b2c0 = b2s[c], b2c1 = b2s[c + 1];
            float cm0 = 3.0e38f, cm1 = 3.0e38f;
            #pragma unroll
            for (int mf = 0; mf < 2; ++mf) {
                const int* i1 = acc1[mf][p];
                const int* i2 = acc2[mf][p];
                float d0 = fmaf(c1a, (float)i1[0], c2a * (float)i2[0]);
                float d1 = fmaf(c1b, (float)i1[1], c2b * (float)i2[1]);
                float d2 = fmaf(c1a, (float)i1[2], c2a * (float)i2[2]);
                float d3 = fmaf(c1b, (float)i1[3], c2b * (float)i2[3]);
                const int r0 = m0 + mf * 16 + (lid >> 2);
                *(float2*)(out + PROTO_OFF + (row0 + r0) * (long)K + c)     = make_float2(d0, d1);
                *(float2*)(out + PROTO_OFF + (row0 + r0 + 8) * (long)K + c) = make_float2(d2, d3);
                float z0 = fmaxf(fmaf(-2.f, d0, a2r[mf][0] + b2c0), 0.f);
                float z1 = fmaxf(fmaf(-2.f, d1, a2r[mf][0] + b2c1), 0.f);
                float z2 = fmaxf(fmaf(-2.f, d2, a2r[mf][1] + b2c0), 0.f);
                float z3 = fmaxf(fmaf(-2.f, d3, a2r[mf][1] + b2c1), 0.f);
                rowmin[mf * 2]     = fminf(rowmin[mf * 2],     fminf(z0, z1));
                rowmin[mf * 2 + 1] = fminf(rowmin[mf * 2 + 1], fminf(z2, z3));
                cm0 = fminf(cm0, fminf(z0, z2));
                cm1 = fminf(cm1, fminf(z1, z3));
            }
            #pragma unroll
            for (int o = 4; o < 32; o <<= 1) {
                cm0 = fminf(cm0, __shfl_xor_sync(0xffffffffu, cm0, o));
                cm1 = fminf(cm1, __shfl_xor_sync(0xffffffffu, cm1, o));
            }
            if (lid < 4) {
                atomicMin(&cmin_s[c],     __float_as_uint(cm0));
                atomicMin(&cmin_s[c + 1], __float_as_uint(cm1));
            }
        }
    }

    // Row-min: quad reduce then smem atomics
    #pragma unroll
    for (int o = 1; o < 4; o <<= 1)
        #pragma unroll
        for (int j = 0; j < 4; ++j)
            rowmin[j] = fminf(rowmin[j], __shfl_xor_sync(0xffffffffu, rowmin[j], o));
    if ((lid & 3) == 0) {
        const int rq = lid >> 2;
        atomicMin(&rmin_s[m0 + rq],      __float_as_uint(rowmin[0]));
        atomicMin(&rmin_s[m0 + rq + 8],  __float_as_uint(rowmin[1]));
        atomicMin(&rmin_s[m0 + 16 + rq], __float_as_uint(rowmin[2]));
        atomicMin(&rmin_s[m0 + 24 + rq], __float_as_uint(rowmin[3]));
    }
    __syncthreads();

    // ---- Phase 4: block reductions -> global scratch ----
    if (t < TILE_M)
        red[t] = sqrtf(fmaxf(__uint_as_float(rmin_s[t]), 1e-12f));
    __syncthreads();
    for (int s = 64; s > 0; s >>= 1) {
        if (t < s) red[t] += red[t + s];
        __syncthreads();
    }
    if (t == 0) g_row_partial[blockIdx.x] = red[0];
    atomicMin(&g_colmin[t],       cmin_s[t]);
    atomicMin(&g_colmin[t + 256], cmin_s[t + 256]);
}

// ---------------------------------------------------------------------------
// Final: deterministic reductions + scalar outputs
// ---------------------------------------------------------------------------
__global__ void swav_final_kernel(const float* __restrict__ recon,
                                  const float* __restrict__ kl,
                                  const float* __restrict__ mmd,
                                  float* __restrict__ out) {
    __shared__ float red[K];
    int t = threadIdx.x;  // 512 threads
    float s = 0.f;
    for (int i = t; i < NBLOCKS; i += K) s += g_row_partial[i];
    red[t] = s;
    __syncthreads();
    for (int st = 256; st > 0; st >>= 1) { if (t < st) red[t] += red[t + st]; __syncthreads(); }
    float rowsum = red[0];
    __syncthreads();

    red[t] = sqrtf(fmaxf(__uint_as_float(g_colmin[t]), 1e-12f));
    __syncthreads();
    for (int st = 256; st > 0; st >>= 1) { if (t < st) red[t] += red[t + st]; __syncthreads(); }

    if (t == 0) {
        float pdl = 0.5f * (rowsum / (float)N_ROWS) + 0.5f * (red[0] / (float)K);
        out[CVAE_OFF] = recon[0] + 0.5f * kl[0] + mmd[0];
        out[PDL_OFF]  = pdl;
    }
}

// ---------------------------------------------------------------------------
extern "C" void kernel_launch(void* const* d_in, const int* in_sizes, int n_in,
                              void* d_out, int out_size) {
    const float* x     = (const float*)d_in[0];
    const float* W     = (const float*)d_in[1];
    const float* recon = (const float*)d_in[2];
    const float* kl    = (const float*)d_in[3];
    const float* mmd   = (const float*)d_in[4];
    float* out = (float*)d_out;

    cudaFuncSetAttribute(swav_main_kernel,
                         cudaFuncAttributeMaxDynamicSharedMemorySize, SMEM_TOTAL);

    swav_init_kernel<<<64, 256>>>(W);
    swav_main_kernel<<<NBLOCKS, 256, SMEM_TOTAL>>>(x, out);
    swav_final_kernel<<<1, K>>>(recon, kl, mmd, out);
}

// round 8
// speedup vs baseline: 1.8352x; 1.8352x over previous
#include <cuda_runtime.h>
#include <cuda_bf16.h>
#include <math.h>
#include <stdint.h>

// ---------------------------------------------------------------------------
// Problem constants
// ---------------------------------------------------------------------------
#define N_ROWS 131072
#define D 64
#define K 512
#define TILE_M 128
#define NBLOCKS (N_ROWS / TILE_M)   // 1024
#define PADB 144                    // bf16 tile row stride in BYTES (64*2 + 16)

// Output layout: [xn | xn | proto | cvae | pdl]
#define XN2_OFF   ((long)N_ROWS * D)
#define PROTO_OFF (2L * N_ROWS * D)
#define CVAE_OFF  (PROTO_OFF + (long)N_ROWS * K)
#define PDL_OFF   (CVAE_OFF + 1)

// Shared memory layout (bytes)
#define OFF_AHI   0                  // bf16 [128] rows x PADB
#define OFF_ALO   18432
#define OFF_WHI   36864              // bf16 [512] rows x PADB
#define OFF_WLO   110592
#define OFF_B2    184320             // f32 [512]
#define OFF_A2    186368             // f32 [128]
#define OFF_CMIN  186880             // u32 [512]
#define OFF_RMIN  188928             // u32 [128]
#define OFF_RED   189440             // f32 [128]
#define SMEM_TOTAL 189952

// Device scratch (no allocations allowed)
__device__ unsigned int g_colmin[K];
__device__ float        g_row_partial[NBLOCKS];
__device__ float        g_b2[K];
__device__ unsigned int g_Whi_img[K * 32];   // packed bf16x2 [512][32]
__device__ unsigned int g_Wlo_img[K * 32];

// ---------------------------------------------------------------------------
// Helpers (sm_80-level PTX only: ldmatrix + mma.sync — no tcgen05)
// ---------------------------------------------------------------------------
__device__ __forceinline__ uint32_t smem_u32(const void* p) {
    uint32_t a;
    asm("{ .reg .u64 t; cvta.to.shared.u64 t, %1; cvt.u32.u64 %0, t; }" : "=r"(a) : "l"(p));
    return a;
}
__device__ __forceinline__ void ldsm_x4(uint32_t* r, uint32_t addr) {
    asm volatile("ldmatrix.sync.aligned.m8n8.x4.shared.b16 {%0,%1,%2,%3}, [%4];"
                 : "=r"(r[0]), "=r"(r[1]), "=r"(r[2]), "=r"(r[3]) : "r"(addr));
}
__device__ __forceinline__ void mma_bf16(float* d, const uint32_t* a, uint32_t b0, uint32_t b1) {
    asm volatile("mma.sync.aligned.m16n8k16.row.col.f32.bf16.bf16.f32 "
                 "{%0,%1,%2,%3}, {%4,%5,%6,%7}, {%8,%9}, {%0,%1,%2,%3};"
                 : "+f"(d[0]), "+f"(d[1]), "+f"(d[2]), "+f"(d[3])
                 : "r"(a[0]), "r"(a[1]), "r"(a[2]), "r"(a[3]), "r"(b0), "r"(b1));
}

// ---------------------------------------------------------------------------
// Init: W -> packed bf16 hi/lo images + b2 + colmin reset. 512 warps.
// ---------------------------------------------------------------------------
__global__ void swav_init_kernel(const float* __restrict__ W) {
    int gt  = blockIdx.x * blockDim.x + threadIdx.x;
    int r   = gt >> 5;
    int lid = gt & 31;
    if (r >= K) return;

    float2 v = *(const float2*)&W[r * D + lid * 2];
    __nv_bfloat16 h0 = __float2bfloat16(v.x);
    __nv_bfloat16 h1 = __float2bfloat16(v.y);
    float l0 = v.x - __bfloat162float(h0);
    float l1 = v.y - __bfloat162float(h1);
    __nv_bfloat162 hp = __nv_bfloat162(h0, h1);
    __nv_bfloat162 lp = __nv_bfloat162(__float2bfloat16(l0), __float2bfloat16(l1));

    g_Whi_img[r * 32 + lid] = *(unsigned int*)&hp;
    g_Wlo_img[r * 32 + lid] = *(unsigned int*)&lp;

    float s = fmaf(v.x, v.x, v.y * v.y);
    #pragma unroll
    for (int o = 16; o > 0; o >>= 1) s += __shfl_xor_sync(0xffffffffu, s, o);
    if (lid == 0) { g_b2[r] = s; g_colmin[r] = 0x7F800000u; }
}

// ---------------------------------------------------------------------------
// Main: per CTA 128 rows x all 512 prototypes.
// normalize (regs) -> xn x2 -> bf16 hi/lo smem tiles -> HMMA split GEMM
// with PRODUCT-MAJOR MMA interleaving (4 independent acc chains) -> epilogue.
// ---------------------------------------------------------------------------
__global__ __launch_bounds__(256, 1)
void swav_main_kernel(const float* __restrict__ x, float* __restrict__ out) {
    extern __shared__ __align__(16) char sm[];
    float*        b2s    = (float*)(sm + OFF_B2);
    float*        a2s    = (float*)(sm + OFF_A2);
    unsigned int* cmin_s = (unsigned int*)(sm + OFF_CMIN);
    unsigned int* rmin_s = (unsigned int*)(sm + OFF_RMIN);
    float*        red    = (float*)(sm + OFF_RED);

    const uint32_t sb  = smem_u32(sm);
    const int t   = threadIdx.x;
    const int lid = t & 31;
    const int wid = t >> 5;
    const long row0 = (long)blockIdx.x * TILE_M;

    // ---- Phase 1: W images -> padded smem tiles; init reductions ----
    {
        const uint4* whi = (const uint4*)g_Whi_img;   // [512*8] uint4
        const uint4* wlo = (const uint4*)g_Wlo_img;
        #pragma unroll
        for (int i = 0; i < 16; ++i) {
            int idx = t + i * 256;            // 4096 uint4
            int r = idx >> 3, c = idx & 7;
            *(uint4*)(sm + OFF_WHI + r * PADB + c * 16) = whi[idx];
            *(uint4*)(sm + OFF_WLO + r * PADB + c * 16) = wlo[idx];
        }
    }
    for (int i = t; i < K; i += 256) { b2s[i] = g_b2[i]; cmin_s[i] = 0x7F800000u; }
    if (t < TILE_M) rmin_s[t] = 0x7F800000u;

    // ---- Phase 2: load x, normalize in registers, write xn x2, build A tiles ----
    {
        const float4* xg  = (const float4*)(x + row0 * D);
        float4* xn1 = (float4*)(out + row0 * D);
        float4* xn2 = (float4*)(out + XN2_OFF + row0 * D);
        float4 v[8]; float s[8];
        #pragma unroll
        for (int i = 0; i < 8; ++i) {
            int idx = t + i * 256;                    // [128 rows][16 float4]
            v[i] = xg[idx];
            s[i] = fmaf(v[i].x, v[i].x, fmaf(v[i].y, v[i].y,
                    fmaf(v[i].z, v[i].z, v[i].w * v[i].w)));
        }
        #pragma unroll
        for (int m = 1; m < 16; m <<= 1)
            #pragma unroll
            for (int i = 0; i < 8; ++i)
                s[i] += __shfl_xor_sync(0xffffffffu, s[i], m);
        #pragma unroll
        for (int i = 0; i < 8; ++i) {
            int idx = t + i * 256;
            int r = idx >> 4, c = idx & 15;
            float inv = 1.0f / fmaxf(sqrtf(s[i]), 1e-12f);
            float4 w4 = make_float4(v[i].x * inv, v[i].y * inv, v[i].z * inv, v[i].w * inv);
            xn1[idx] = w4;
            xn2[idx] = w4;
            if ((t & 15) == 0) a2s[r] = s[i] * inv * inv;

            __nv_bfloat16 hx = __float2bfloat16(w4.x), hy = __float2bfloat16(w4.y);
            __nv_bfloat16 hz = __float2bfloat16(w4.z), hw = __float2bfloat16(w4.w);
            __nv_bfloat162 hp0 = __nv_bfloat162(hx, hy);
            __nv_bfloat162 hp1 = __nv_bfloat162(hz, hw);
            __nv_bfloat162 lp0 = __nv_bfloat162(__float2bfloat16(w4.x - __bfloat162float(hx)),
                                                __float2bfloat16(w4.y - __bfloat162float(hy)));
            __nv_bfloat162 lp1 = __nv_bfloat162(__float2bfloat16(w4.z - __bfloat162float(hz)),
                                                __float2bfloat16(w4.w - __bfloat162float(hw)));
            uint2 hh = make_uint2(*(unsigned*)&hp0, *(unsigned*)&hp1);
            uint2 ll = make_uint2(*(unsigned*)&lp0, *(unsigned*)&lp1);
            *(uint2*)(sm + OFF_AHI + r * PADB + c * 8) = hh;
            *(uint2*)(sm + OFF_ALO + r * PADB + c * 8) = ll;
        }
    }
    __syncthreads();

    // ---- Phase 3: HMMA split GEMM + epilogue, two column halves ----
    const int wy = wid & 3, wx = wid >> 2;
    const int m0 = wy * 32;

    // ldmatrix lane addressing
    const uint32_t a_off  = (uint32_t)(m0 + (lid & 15)) * PADB + ((lid >> 4) * 16);
    const uint32_t aaddr_hi = sb + OFF_AHI + a_off;
    const uint32_t aaddr_lo = sb + OFF_ALO + a_off;
    const uint32_t b_rowi = ((lid >> 4) << 3) + (lid & 7);
    const uint32_t b_koff = ((lid >> 3) & 1) * 16;

    float a2r[2][2];
    #pragma unroll
    for (int mf = 0; mf < 2; ++mf) {
        a2r[mf][0] = a2s[m0 + mf * 16 + (lid >> 2)];
        a2r[mf][1] = a2s[m0 + mf * 16 + (lid >> 2) + 8];
    }

    float rowmin[4];
    #pragma unroll
    for (int j = 0; j < 4; ++j) rowmin[j] = 3.0e38f;

    for (int h = 0; h < 2; ++h) {
        const int nb = h * 256 + wx * 128;
        float acc[2][16][4];
        #pragma unroll
        for (int mf = 0; mf < 2; ++mf)
            #pragma unroll
            for (int p = 0; p < 16; ++p)
                #pragma unroll
                for (int q = 0; q < 4; ++q) acc[mf][p][q] = 0.f;

        #pragma unroll 1
        for (int k = 0; k < 4; ++k) {
            const uint32_t ka = (uint32_t)k * 32;
            uint32_t ah[2][4], al[2][4];
            ldsm_x4(ah[0], aaddr_hi + ka);
            ldsm_x4(ah[1], aaddr_hi + 16 * PADB + ka);
            ldsm_x4(al[0], aaddr_lo + ka);
            ldsm_x4(al[1], aaddr_lo + 16 * PADB + ka);
            #pragma unroll
            for (int p = 0; p < 8; ++p) {
                uint32_t baddr = sb + OFF_WHI +
                    (uint32_t)(nb + p * 16 + b_rowi) * PADB + b_koff + ka;
                uint32_t bh[4], bl[4];
                ldsm_x4(bh, baddr);
                ldsm_x4(bl, baddr + (OFF_WLO - OFF_WHI));
                // Product-major interleave: 4 independent accumulator chains
                // (mf0/frag0, mf0/frag1, mf1/frag0, mf1/frag1); each chain's
                // 3 dependent MMAs are spaced 4 issue slots apart.
                mma_bf16(acc[0][2 * p],     ah[0], bh[0], bh[1]);   // hh
                mma_bf16(acc[0][2 * p + 1], ah[0], bh[2], bh[3]);
                mma_bf16(acc[1][2 * p],     ah[1], bh[0], bh[1]);
                mma_bf16(acc[1][2 * p + 1], ah[1], bh[2], bh[3]);
                mma_bf16(acc[0][2 * p],     ah[0], bl[0], bl[1]);   // hl
                mma_bf16(acc[0][2 * p + 1], ah[0], bl[2], bl[3]);
                mma_bf16(acc[1][2 * p],     ah[1], bl[0], bl[1]);
                mma_bf16(acc[1][2 * p + 1], ah[1], bl[2], bl[3]);
                mma_bf16(acc[0][2 * p],     al[0], bh[0], bh[1]);   // lh
                mma_bf16(acc[0][2 * p + 1], al[0], bh[2], bh[3]);
                mma_bf16(acc[1][2 * p],     al[1], bh[0], bh[1]);
                mma_bf16(acc[1][2 * p + 1], al[1], bh[2], bh[3]);
            }
        }

        // Epilogue: proto stores + z-mins, all from registers
        #pragma unroll
        for (int p = 0; p < 16; ++p) {
            const int c = nb + p * 8 + 2 * (lid & 3);
            const float b2c0 = b2s[c], b2c1 = b2s[c + 1];
            float cm0 = 3.0e38f, cm1 = 3.0e38f;
            #pragma unroll
            for (int mf = 0; mf < 2; ++mf) {
                float* d = acc[mf][p];
                const int r0 = m0 + mf * 16 + (lid >> 2);
                *(float2*)(out + PROTO_OFF + (row0 + r0) * (long)K + c)
                    = make_float2(d[0], d[1]);
                *(float2*)(out + PROTO_OFF + (row0 + r0 + 8) * (long)K + c)
                    = make_float2(d[2], d[3]);
                float z0 = fmaxf(fmaf(-2.f, d[0], a2r[mf][0] + b2c0), 0.f);
                float z1 = fmaxf(fmaf(-2.f, d[1], a2r[mf][0] + b2c1), 0.f);
                float z2 = fmaxf(fmaf(-2.f, d[2], a2r[mf][1] + b2c0), 0.f);
                float z3 = fmaxf(fmaf(-2.f, d[3], a2r[mf][1] + b2c1), 0.f);
                rowmin[mf * 2]     = fminf(rowmin[mf * 2],     fminf(z0, z1));
                rowmin[mf * 2 + 1] = fminf(rowmin[mf * 2 + 1], fminf(z2, z3));
                cm0 = fminf(cm0, fminf(z0, z2));
                cm1 = fminf(cm1, fminf(z1, z3));
            }
            #pragma unroll
            for (int o = 4; o < 32; o <<= 1) {
                cm0 = fminf(cm0, __shfl_xor_sync(0xffffffffu, cm0, o));
                cm1 = fminf(cm1, __shfl_xor_sync(0xffffffffu, cm1, o));
            }
            if (lid < 4) {
                atomicMin(&cmin_s[c],     __float_as_uint(cm0));
                atomicMin(&cmin_s[c + 1], __float_as_uint(cm1));
            }
        }
    }

    // Row-min: reduce across the 4 lanes of each quad, then smem atomics
    #pragma unroll
    for (int o = 1; o < 4; o <<= 1)
        #pragma unroll
        for (int j = 0; j < 4; ++j)
            rowmin[j] = fminf(rowmin[j], __shfl_xor_sync(0xffffffffu, rowmin[j], o));
    if ((lid & 3) == 0) {
        const int rq = lid >> 2;
        atomicMin(&rmin_s[m0 + rq],      __float_as_uint(rowmin[0]));
        atomicMin(&rmin_s[m0 + rq + 8],  __float_as_uint(rowmin[1]));
        atomicMin(&rmin_s[m0 + 16 + rq], __float_as_uint(rowmin[2]));
        atomicMin(&rmin_s[m0 + 24 + rq], __float_as_uint(rowmin[3]));
    }
    __syncthreads();

    // ---- Phase 4: block reductions -> global scratch ----
    if (t < TILE_M)
        red[t] = sqrtf(fmaxf(__uint_as_float(rmin_s[t]), 1e-12f));
    __syncthreads();
    for (int s = 64; s > 0; s >>= 1) {
        if (t < s) red[t] += red[t + s];
        __syncthreads();
    }
    if (t == 0) g_row_partial[blockIdx.x] = red[0];
    atomicMin(&g_colmin[t],       cmin_s[t]);
    atomicMin(&g_colmin[t + 256], cmin_s[t + 256]);
}

// ---------------------------------------------------------------------------
// Final: deterministic reductions + scalar outputs
// ---------------------------------------------------------------------------
__global__ void swav_final_kernel(const float* __restrict__ recon,
                                  const float* __restrict__ kl,
                                  const float* __restrict__ mmd,
                                  float* __restrict__ out) {
    __shared__ float red[K];
    int t = threadIdx.x;  // 512 threads
    float s = 0.f;
    for (int i = t; i < NBLOCKS; i += K) s += g_row_partial[i];
    red[t] = s;
    __syncthreads();
    for (int st = 256; st > 0; st >>= 1) { if (t < st) red[t] += red[t + st]; __syncthreads(); }
    float rowsum = red[0];
    __syncthreads();

    red[t] = sqrtf(fmaxf(__uint_as_float(g_colmin[t]), 1e-12f));
    __syncthreads();
    for (int st = 256; st > 0; st >>= 1) { if (t < st) red[t] += red[t + st]; __syncthreads(); }

    if (t == 0) {
        float pdl = 0.5f * (rowsum / (float)N_ROWS) + 0.5f * (red[0] / (float)K);
        out[CVAE_OFF] = recon[0] + 0.5f * kl[0] + mmd[0];
        out[PDL_OFF]  = pdl;
    }
}

// ---------------------------------------------------------------------------
extern "C" void kernel_launch(void* const* d_in, const int* in_sizes, int n_in,
                              void* d_out, int out_size) {
    const float* x     = (const float*)d_in[0];
    const float* W     = (const float*)d_in[1];
    const float* recon = (const float*)d_in[2];
    const float* kl    = (const float*)d_in[3];
    const float* mmd   = (const float*)d_in[4];
    float* out = (float*)d_out;

    cudaFuncSetAttribute(swav_main_kernel,
                         cudaFuncAttributeMaxDynamicSharedMemorySize, SMEM_TOTAL);

    swav_init_kernel<<<64, 256>>>(W);
    swav_main_kernel<<<NBLOCKS, 256, SMEM_TOTAL>>>(x, out);
    swav_final_kernel<<<1, K>>>(recon, kl, mmd, out);
}

// round 9
// speedup vs baseline: 2.0265x; 1.1043x over previous
#include <cuda_runtime.h>
#include <cuda_bf16.h>
#include <math.h>
#include <stdint.h>

// ---------------------------------------------------------------------------
// Problem constants
// ---------------------------------------------------------------------------
#define N_ROWS 131072
#define D 64
#define K 512
#define TILE_M 128
#define NTILES (N_ROWS / TILE_M)    // 1024
#define PADB 144                    // bf16 tile row stride in BYTES (64*2 + 16)

// Output layout: [xn | xn | proto | cvae | pdl]
#define XN2_OFF   ((long)N_ROWS * D)
#define PROTO_OFF (2L * N_ROWS * D)
#define CVAE_OFF  (PROTO_OFF + (long)N_ROWS * K)
#define PDL_OFF   (CVAE_OFF + 1)

// Shared memory layout (bytes)
#define OFF_AHI   0                  // bf16 [128] rows x PADB
#define OFF_ALO   18432
#define OFF_WHI   36864              // bf16 [512] rows x PADB (resident)
#define OFF_WLO   110592
#define OFF_B2    184320             // f32 [512]
#define OFF_A2    186368             // f32 [128]
#define OFF_CMIN  186880             // u32 [512]  (persistent across tiles)
#define OFF_RMIN  188928             // u32 [128]  (per tile)
#define OFF_RED   189440             // f32 [128]
#define OFF_XS    189952             // f32 x staging [128][64] = 32768 (cp.async)
#define SMEM_TOTAL 222720

// Device scratch (no allocations allowed)
__device__ unsigned int g_colmin[K];
__device__ float        g_row_partial[NTILES];
__device__ float        g_b2[K];
__device__ unsigned int g_Whi_img[K * 32];   // packed bf16x2 [512][32]
__device__ unsigned int g_Wlo_img[K * 32];

// ---------------------------------------------------------------------------
// Helpers (sm_80-level PTX only: ldmatrix + mma.sync + cp.async)
// ---------------------------------------------------------------------------
__device__ __forceinline__ uint32_t smem_u32(const void* p) {
    uint32_t a;
    asm("{ .reg .u64 t; cvta.to.shared.u64 t, %1; cvt.u32.u64 %0, t; }" : "=r"(a) : "l"(p));
    return a;
}
__device__ __forceinline__ void ldsm_x4(uint32_t* r, uint32_t addr) {
    asm volatile("ldmatrix.sync.aligned.m8n8.x4.shared.b16 {%0,%1,%2,%3}, [%4];"
                 : "=r"(r[0]), "=r"(r[1]), "=r"(r[2]), "=r"(r[3]) : "r"(addr));
}
__device__ __forceinline__ void mma_bf16(float* d, const uint32_t* a, uint32_t b0, uint32_t b1) {
    asm volatile("mma.sync.aligned.m16n8k16.row.col.f32.bf16.bf16.f32 "
                 "{%0,%1,%2,%3}, {%4,%5,%6,%7}, {%8,%9}, {%0,%1,%2,%3};"
                 : "+f"(d[0]), "+f"(d[1]), "+f"(d[2]), "+f"(d[3])
                 : "r"(a[0]), "r"(a[1]), "r"(a[2]), "r"(a[3]), "r"(b0), "r"(b1));
}
__device__ __forceinline__ void cp_async16(uint32_t saddr, const void* gptr) {
    asm volatile("cp.async.cg.shared.global [%0], [%1], 16;"
                 :: "r"(saddr), "l"(gptr) : "memory");
}
#define CP_COMMIT()   asm volatile("cp.async.commit_group;" ::: "memory")
#define CP_WAIT_ALL() asm volatile("cp.async.wait_all;" ::: "memory")

// ---------------------------------------------------------------------------
// Init: W -> packed bf16 hi/lo images + b2 + colmin reset. 512 warps.
// ---------------------------------------------------------------------------
__global__ void swav_init_kernel(const float* __restrict__ W) {
    int gt  = blockIdx.x * blockDim.x + threadIdx.x;
    int r   = gt >> 5;
    int lid = gt & 31;
    if (r >= K) return;

    float2 v = *(const float2*)&W[r * D + lid * 2];
    __nv_bfloat16 h0 = __float2bfloat16(v.x);
    __nv_bfloat16 h1 = __float2bfloat16(v.y);
    float l0 = v.x - __bfloat162float(h0);
    float l1 = v.y - __bfloat162float(h1);
    __nv_bfloat162 hp = __nv_bfloat162(h0, h1);
    __nv_bfloat162 lp = __nv_bfloat162(__float2bfloat16(l0), __float2bfloat16(l1));

    g_Whi_img[r * 32 + lid] = *(unsigned int*)&hp;
    g_Wlo_img[r * 32 + lid] = *(unsigned int*)&lp;

    float s = fmaf(v.x, v.x, v.y * v.y);
    #pragma unroll
    for (int o = 16; o > 0; o >>= 1) s += __shfl_xor_sync(0xffffffffu, s, o);
    if (lid == 0) { g_b2[r] = s; g_colmin[r] = 0x7F800000u; }
}

// ---------------------------------------------------------------------------
// Main: PERSISTENT CTAs. W resident in smem; x staged ahead via cp.async.
// Per tile: normalize -> xn x2 -> bf16 hi/lo A tiles -> interleaved HMMA
// split GEMM -> register epilogue (proto + z-mins) -> per-tile row reduce.
// ---------------------------------------------------------------------------
__global__ __launch_bounds__(256, 1)
void swav_main_kernel(const float* __restrict__ x, float* __restrict__ out,
                      int nsm) {
    extern __shared__ __align__(16) char sm[];
    float*        b2s    = (float*)(sm + OFF_B2);
    float*        a2s    = (float*)(sm + OFF_A2);
    unsigned int* cmin_s = (unsigned int*)(sm + OFF_CMIN);
    unsigned int* rmin_s = (unsigned int*)(sm + OFF_RMIN);
    float*        red    = (float*)(sm + OFF_RED);

    const uint32_t sb  = smem_u32(sm);
    const int t   = threadIdx.x;
    const int lid = t & 31;
    const int wid = t >> 5;

    // ---- One-time: W images -> padded smem tiles; scalars; first x prefetch ----
    {
        const uint4* whi = (const uint4*)g_Whi_img;   // [512*8] uint4
        const uint4* wlo = (const uint4*)g_Wlo_img;
        #pragma unroll
        for (int i = 0; i < 16; ++i) {
            int idx = t + i * 256;            // 4096 uint4
            int r = idx >> 3, c = idx & 7;
            *(uint4*)(sm + OFF_WHI + r * PADB + c * 16) = whi[idx];
            *(uint4*)(sm + OFF_WLO + r * PADB + c * 16) = wlo[idx];
        }
    }
    for (int i = t; i < K; i += 256) { b2s[i] = g_b2[i]; cmin_s[i] = 0x7F800000u; }

    // Prefetch x for first tile
    {
        int tile0 = blockIdx.x;
        if (tile0 < NTILES) {
            const char* gx = (const char*)(x + (long)tile0 * TILE_M * D);
            #pragma unroll
            for (int i = 0; i < 8; ++i) {
                int idx = t + i * 256;
                cp_async16(sb + OFF_XS + idx * 16, gx + (long)idx * 16);
            }
        }
        CP_COMMIT();
    }

    // ldmatrix lane addressing (tile-invariant)
    const int wy = wid & 3, wx = wid >> 2;
    const int m0 = wy * 32;
    const uint32_t a_off    = (uint32_t)(m0 + (lid & 15)) * PADB + ((lid >> 4) * 16);
    const uint32_t aaddr_hi = sb + OFF_AHI + a_off;
    const uint32_t aaddr_lo = sb + OFF_ALO + a_off;
    const uint32_t b_rowi   = ((lid >> 4) << 3) + (lid & 7);
    const uint32_t b_koff   = ((lid >> 3) & 1) * 16;

    // ================= persistent tile loop =================
    for (int tile = blockIdx.x; tile < NTILES; tile += nsm) {
        const long row0 = (long)tile * TILE_M;

        CP_WAIT_ALL();
        __syncthreads();

        // ---- read staged x into regs ----
        float4 v[8]; float s[8];
        #pragma unroll
        for (int i = 0; i < 8; ++i) {
            int idx = t + i * 256;                    // [128 rows][16 float4]
            v[i] = *(const float4*)(sm + OFF_XS + idx * 16);
            s[i] = fmaf(v[i].x, v[i].x, fmaf(v[i].y, v[i].y,
                    fmaf(v[i].z, v[i].z, v[i].w * v[i].w)));
        }
        __syncthreads();   // staging consumed -> safe to overwrite

        // ---- prefetch next tile's x (overlaps with pack + GEMM) ----
        {
            int nxt = tile + nsm;
            if (nxt < NTILES) {
                const char* gx = (const char*)(x + (long)nxt * TILE_M * D);
                #pragma unroll
                for (int i = 0; i < 8; ++i) {
                    int idx = t + i * 256;
                    cp_async16(sb + OFF_XS + idx * 16, gx + (long)idx * 16);
                }
            }
            CP_COMMIT();
        }

        // ---- normalize, write xn x2, build A hi/lo tiles ----
        #pragma unroll
        for (int m = 1; m < 16; m <<= 1)
            #pragma unroll
            for (int i = 0; i < 8; ++i)
                s[i] += __shfl_xor_sync(0xffffffffu, s[i], m);
        {
            float4* xn1 = (float4*)(out + row0 * D);
            float4* xn2 = (float4*)(out + XN2_OFF + row0 * D);
            #pragma unroll
            for (int i = 0; i < 8; ++i) {
                int idx = t + i * 256;
                int r = idx >> 4, c = idx & 15;
                float inv = 1.0f / fmaxf(sqrtf(s[i]), 1e-12f);
                float4 w4 = make_float4(v[i].x * inv, v[i].y * inv,
                                        v[i].z * inv, v[i].w * inv);
                xn1[idx] = w4;
                xn2[idx] = w4;
                if ((t & 15) == 0) a2s[r] = s[i] * inv * inv;

                __nv_bfloat16 hx = __float2bfloat16(w4.x), hy = __float2bfloat16(w4.y);
                __nv_bfloat16 hz = __float2bfloat16(w4.z), hw = __float2bfloat16(w4.w);
                __nv_bfloat162 hp0 = __nv_bfloat162(hx, hy);
                __nv_bfloat162 hp1 = __nv_bfloat162(hz, hw);
                __nv_bfloat162 lp0 = __nv_bfloat162(__float2bfloat16(w4.x - __bfloat162float(hx)),
                                                    __float2bfloat16(w4.y - __bfloat162float(hy)));
                __nv_bfloat162 lp1 = __nv_bfloat162(__float2bfloat16(w4.z - __bfloat162float(hz)),
                                                    __float2bfloat16(w4.w - __bfloat162float(hw)));
                uint2 hh = make_uint2(*(unsigned*)&hp0, *(unsigned*)&hp1);
                uint2 ll = make_uint2(*(unsigned*)&lp0, *(unsigned*)&lp1);
                *(uint2*)(sm + OFF_AHI + r * PADB + c * 8) = hh;
                *(uint2*)(sm + OFF_ALO + r * PADB + c * 8) = ll;
            }
        }
        if (t < TILE_M) rmin_s[t] = 0x7F800000u;
        __syncthreads();

        // ---- HMMA split GEMM + epilogue, two column halves ----
        float a2r[2][2];
        #pragma unroll
        for (int mf = 0; mf < 2; ++mf) {
            a2r[mf][0] = a2s[m0 + mf * 16 + (lid >> 2)];
            a2r[mf][1] = a2s[m0 + mf * 16 + (lid >> 2) + 8];
        }
        float rowmin[4];
        #pragma unroll
        for (int j = 0; j < 4; ++j) rowmin[j] = 3.0e38f;

        for (int h = 0; h < 2; ++h) {
            const int nb = h * 256 + wx * 128;
            float acc[2][16][4];
            #pragma unroll
            for (int mf = 0; mf < 2; ++mf)
                #pragma unroll
                for (int p = 0; p < 16; ++p)
                    #pragma unroll
                    for (int q = 0; q < 4; ++q) acc[mf][p][q] = 0.f;

            #pragma unroll 1
            for (int k = 0; k < 4; ++k) {
                const uint32_t ka = (uint32_t)k * 32;
                uint32_t ah[2][4], al[2][4];
                ldsm_x4(ah[0], aaddr_hi + ka);
                ldsm_x4(ah[1], aaddr_hi + 16 * PADB + ka);
                ldsm_x4(al[0], aaddr_lo + ka);
                ldsm_x4(al[1], aaddr_lo + 16 * PADB + ka);
                #pragma unroll
                for (int p = 0; p < 8; ++p) {
                    uint32_t baddr = sb + OFF_WHI +
                        (uint32_t)(nb + p * 16 + b_rowi) * PADB + b_koff + ka;
                    uint32_t bh[4], bl[4];
                    ldsm_x4(bh, baddr);
                    ldsm_x4(bl, baddr + (OFF_WLO - OFF_WHI));
                    // Product-major interleave: 4 independent accumulator chains
                    mma_bf16(acc[0][2 * p],     ah[0], bh[0], bh[1]);   // hh
                    mma_bf16(acc[0][2 * p + 1], ah[0], bh[2], bh[3]);
                    mma_bf16(acc[1][2 * p],     ah[1], bh[0], bh[1]);
                    mma_bf16(acc[1][2 * p + 1], ah[1], bh[2], bh[3]);
                    mma_bf16(acc[0][2 * p],     ah[0], bl[0], bl[1]);   // hl
                    mma_bf16(acc[0][2 * p + 1], ah[0], bl[2], bl[3]);
                    mma_bf16(acc[1][2 * p],     ah[1], bl[0], bl[1]);
                    mma_bf16(acc[1][2 * p + 1], ah[1], bl[2], bl[3]);
                    mma_bf16(acc[0][2 * p],     al[0], bh[0], bh[1]);   // lh
                    mma_bf16(acc[0][2 * p + 1], al[0], bh[2], bh[3]);
                    mma_bf16(acc[1][2 * p],     al[1], bh[0], bh[1]);
                    mma_bf16(acc[1][2 * p + 1], al[1], bh[2], bh[3]);
                }
            }

            // Epilogue: proto stores + z-mins, all from registers
            #pragma unroll
            for (int p = 0; p < 16; ++p) {
                const int c = nb + p * 8 + 2 * (lid & 3);
                const float b2c0 = b2s[c], b2c1 = b2s[c + 1];
                float cm0 = 3.0e38f, cm1 = 3.0e38f;
                #pragma unroll
                for (int mf = 0; mf < 2; ++mf) {
                    float* d = acc[mf][p];
                    const int r0 = m0 + mf * 16 + (lid >> 2);
                    *(float2*)(out + PROTO_OFF + (row0 + r0) * (long)K + c)
                        = make_float2(d[0], d[1]);
                    *(float2*)(out + PROTO_OFF + (row0 + r0 + 8) * (long)K + c)
                        = make_float2(d[2], d[3]);
                    float z0 = fmaxf(fmaf(-2.f, d[0], a2r[mf][0] + b2c0), 0.f);
                    float z1 = fmaxf(fmaf(-2.f, d[1], a2r[mf][0] + b2c1), 0.f);
                    float z2 = fmaxf(fmaf(-2.f, d[2], a2r[mf][1] + b2c0), 0.f);
                    float z3 = fmaxf(fmaf(-2.f, d[3], a2r[mf][1] + b2c1), 0.f);
                    rowmin[mf * 2]     = fminf(rowmin[mf * 2],     fminf(z0, z1));
                    rowmin[mf * 2 + 1] = fminf(rowmin[mf * 2 + 1], fminf(z2, z3));
                    cm0 = fminf(cm0, fminf(z0, z2));
                    cm1 = fminf(cm1, fminf(z1, z3));
                }
                #pragma unroll
                for (int o = 4; o < 32; o <<= 1) {
                    cm0 = fminf(cm0, __shfl_xor_sync(0xffffffffu, cm0, o));
                    cm1 = fminf(cm1, __shfl_xor_sync(0xffffffffu, cm1, o));
                }
                if (lid < 4) {
                    atomicMin(&cmin_s[c],     __float_as_uint(cm0));
                    atomicMin(&cmin_s[c + 1], __float_as_uint(cm1));
                }
            }
        }

        // Row-min: quad reduce then smem atomics
        #pragma unroll
        for (int o = 1; o < 4; o <<= 1)
            #pragma unroll
            for (int j = 0; j < 4; ++j)
                rowmin[j] = fminf(rowmin[j], __shfl_xor_sync(0xffffffffu, rowmin[j], o));
        if ((lid & 3) == 0) {
            const int rq = lid >> 2;
            atomicMin(&rmin_s[m0 + rq],      __float_as_uint(rowmin[0]));
            atomicMin(&rmin_s[m0 + rq + 8],  __float_as_uint(rowmin[1]));
            atomicMin(&rmin_s[m0 + 16 + rq], __float_as_uint(rowmin[2]));
            atomicMin(&rmin_s[m0 + 24 + rq], __float_as_uint(rowmin[3]));
        }
        __syncthreads();

        // Per-tile row reduction -> g_row_partial[tile]
        if (t < TILE_M)
            red[t] = sqrtf(fmaxf(__uint_as_float(rmin_s[t]), 1e-12f));
        __syncthreads();
        for (int st = 64; st > 0; st >>= 1) {
            if (t < st) red[t] += red[t + st];
            __syncthreads();
        }
        if (t == 0) g_row_partial[tile] = red[0];
        __syncthreads();
    }

    // ---- merge per-CTA column mins into global (once) ----
    atomicMin(&g_colmin[t],       cmin_s[t]);
    atomicMin(&g_colmin[t + 256], cmin_s[t + 256]);
}

// ---------------------------------------------------------------------------
// Final: deterministic reductions + scalar outputs
// ---------------------------------------------------------------------------
__global__ void swav_final_kernel(const float* __restrict__ recon,
                                  const float* __restrict__ kl,
                                  const float* __restrict__ mmd,
                                  float* __restrict__ out) {
    __shared__ float red[K];
    int t = threadIdx.x;  // 512 threads
    float s = 0.f;
    for (int i = t; i < NTILES; i += K) s += g_row_partial[i];
    red[t] = s;
    __syncthreads();
    for (int st = 256; st > 0; st >>= 1) { if (t < st) red[t] += red[t + st]; __syncthreads(); }
    float rowsum = red[0];
    __syncthreads();

    red[t] = sqrtf(fmaxf(__uint_as_float(g_colmin[t]), 1e-12f));
    __syncthreads();
    for (int st = 256; st > 0; st >>= 1) { if (t < st) red[t] += red[t + st]; __syncthreads(); }

    if (t == 0) {
        float pdl = 0.5f * (rowsum / (float)N_ROWS) + 0.5f * (red[0] / (float)K);
        out[CVAE_OFF] = recon[0] + 0.5f * kl[0] + mmd[0];
        out[PDL_OFF]  = pdl;
    }
}

// ---------------------------------------------------------------------------
extern "C" void kernel_launch(void* const* d_in, const int* in_sizes, int n_in,
                              void* d_out, int out_size) {
    const float* x     = (const float*)d_in[0];
    const float* W     = (const float*)d_in[1];
    const float* recon = (const float*)d_in[2];
    const float* kl    = (const float*)d_in[3];
    const float* mmd   = (const float*)d_in[4];
    float* out = (float*)d_out;

    static int nsm = 0;
    if (nsm == 0) {
        cudaDeviceGetAttribute(&nsm, cudaDevAttrMultiProcessorCount, 0);
        if (nsm <= 0) nsm = 148;
        cudaFuncSetAttribute(swav_main_kernel,
                             cudaFuncAttributeMaxDynamicSharedMemorySize, SMEM_TOTAL);
    }

    swav_init_kernel<<<64, 256>>>(W);
    swav_main_kernel<<<nsm, 256, SMEM_TOTAL>>>(x, out, nsm);
    swav_final_kernel<<<1, K>>>(recon, kl, mmd, out);
}